// round 4
// baseline (speedup 1.0000x reference)
#include <cuda_runtime.h>
#include <cuda_bf16.h>
#include <cstdint>

#define B_   4
#define C_   2048
#define HW_  196
#define M_   784          // B_*HW_
#define MPAD 896          // 7*128
#define NCLS 80
#define WD   300
#define ID   1024

// ---------------- scratch (static device globals; no allocs) ----------------
__device__ float g_v[ID];                   // fc4_w @ fc3_w
__device__ float g_wordp[NCLS * ID];        // word_features @ fc2_w^T
__device__ float g_imgp[M_ * ID];           // x @ fc1_w^T
__device__ float g_logits[B_ * NCLS * HW_]; // [b][n][hw], softmaxed in place
// bf16 hi/lo splits, K-major rows of 2048 (16B-aligned for cp.async)
__device__ __align__(16) unsigned short g_ahi[MPAD * C_];
__device__ __align__(16) unsigned short g_alo[MPAD * C_];
__device__ __align__(16) unsigned short g_bhi[ID * C_];
__device__ __align__(16) unsigned short g_blo[ID * C_];

__device__ __forceinline__ uint32_t smem_u32(const void* p) {
    return (uint32_t)__cvta_generic_to_shared(p);
}

// ---------------- K_prep: fused split_a | split_b | v | wordp (independent roles) ----
// blocks [0,256)      : split+transpose img -> a_hi/a_lo   (b = bx>>6, c0 = (bx&63)*32)
// blocks [256,2304)   : split fc1_w -> b_hi/b_lo
// blocks [2304,2368)  : v[d] = fc4_w @ fc3_w
// blocks [2368,2688)  : wordp[n,d] = dot(wf[n,:], fc2_w[d,:])  thread-per-output
#define PREP_BLOCKS 2688

__global__ void __launch_bounds__(256) k_prep(const float* __restrict__ img,
                                              const float* __restrict__ wf,
                                              const float* __restrict__ fc1w,
                                              const float* __restrict__ fc2w,
                                              const float* __restrict__ fc3w,
                                              const float* __restrict__ fc4w) {
    __shared__ float s[32 * 197];   // split_a transpose buffer; v reuses first 256
    int bx = blockIdx.x;
    int tid = threadIdx.x;

    if (bx < 256) {
        // ---- split_a ----
        int b = bx >> 6, c0 = (bx & 63) * 32;
        for (int e = tid; e < 32 * HW_; e += 256) {
            int ci = e / HW_, hw = e - ci * HW_;
            s[ci * 197 + hw] = img[((long)b * C_ + c0 + ci) * HW_ + hw];
        }
        __syncthreads();
        int ci = tid & 31, hw0 = tid >> 5;
        for (int hw = hw0; hw < HW_; hw += 8) {
            float x = s[ci * 197 + hw];
            __nv_bfloat16 h = __float2bfloat16_rn(x);
            __nv_bfloat16 l = __float2bfloat16_rn(x - __bfloat162float(h));
            long o = (long)(b * HW_ + hw) * C_ + c0 + ci;
            g_ahi[o] = __bfloat16_as_ushort(h);
            g_alo[o] = __bfloat16_as_ushort(l);
        }
    } else if (bx < 2304) {
        // ---- split_b ----
        int idx = (bx - 256) * 256 + tid;    // float4 index, ID*C_/4 total
        float4 v = ((const float4*)fc1w)[idx];
        float vv[4] = {v.x, v.y, v.z, v.w};
        unsigned h[4], l[4];
#pragma unroll
        for (int i = 0; i < 4; i++) {
            __nv_bfloat16 hh = __float2bfloat16_rn(vv[i]);
            __nv_bfloat16 ll = __float2bfloat16_rn(vv[i] - __bfloat162float(hh));
            h[i] = __bfloat16_as_ushort(hh);
            l[i] = __bfloat16_as_ushort(ll);
        }
        ((uint2*)g_bhi)[idx] = make_uint2(h[0] | (h[1] << 16), h[2] | (h[3] << 16));
        ((uint2*)g_blo)[idx] = make_uint2(l[0] | (l[1] << 16), l[2] | (l[3] << 16));
    } else if (bx < 2368) {
        // ---- v ----
        int d0 = (bx - 2304) * 16;
        int dl = tid & 15;
        int eg = tid >> 4;
        int d  = d0 + dl;
        float acc = 0.f;
        int e0 = eg * 64;
#pragma unroll 8
        for (int e = e0; e < e0 + 64; e++)
            acc = fmaf(fc4w[e], fc3w[e * ID + d], acc);
        s[tid] = acc;
        __syncthreads();
        if (tid < 16) {
            float sum = 0.f;
#pragma unroll
            for (int g = 0; g < 16; g++) sum += s[g * 16 + tid];
            g_v[d0 + tid] = sum;
        }
    } else {
        // ---- wordp: thread-per-output ----
        int idx = (bx - 2368) * 256 + tid;   // 0 .. 81919
        int n = idx >> 10;
        int d = idx & 1023;
        const float* wrow = wf + n * WD;
        const float* frow = fc2w + d * WD;
        float acc = 0.f;
#pragma unroll 4
        for (int k = 0; k < WD; k++)
            acc = fmaf(__ldg(wrow + k), frow[k], acc);
        g_wordp[n * ID + d] = acc;
    }
}

// ---------------- K3: bf16 mma.sync GEMM, 3-term split as K=6144 ----------------
// block 128(M) x 64(N), 8 warps (4x2 of 32x32), K-chunk 32, 4-stage cp.async
#define STAGE_BYTES 12288     // A 128x32x2 = 8192, B 64x32x2 = 4096
#define NCHUNK 192            // 3 terms * 64 chunks

__device__ __forceinline__ void cp16(uint32_t s, const void* g) {
    asm volatile("cp.async.cg.shared.global [%0], [%1], 16;" :: "r"(s), "l"(g));
}
__device__ __forceinline__ void ldm4(uint32_t* r, uint32_t a) {
    asm volatile("ldmatrix.sync.aligned.m8n8.x4.shared.b16 {%0,%1,%2,%3}, [%4];"
                 : "=r"(r[0]), "=r"(r[1]), "=r"(r[2]), "=r"(r[3]) : "r"(a));
}
__device__ __forceinline__ void mma16816(float* c, const uint32_t* a, uint32_t b0, uint32_t b1) {
    asm volatile("mma.sync.aligned.m16n8k16.row.col.f32.bf16.bf16.f32 "
                 "{%0,%1,%2,%3}, {%4,%5,%6,%7}, {%8,%9}, {%0,%1,%2,%3};"
                 : "+f"(c[0]), "+f"(c[1]), "+f"(c[2]), "+f"(c[3])
                 : "r"(a[0]), "r"(a[1]), "r"(a[2]), "r"(a[3]), "r"(b0), "r"(b1));
}

__global__ void __launch_bounds__(256) k_mma() {
    __shared__ __align__(128) char smem[4][STAGE_BYTES];
    uint32_t sbase = smem_u32(smem);
    int tid = threadIdx.x;
    int lane = tid & 31, wid = tid >> 5;
    int warp_m = wid >> 1, warp_n = wid & 1;
    int m0 = blockIdx.y * 128, n0 = blockIdx.x * 64;

    // ---- loader mapping (per thread): A rows ar, ar+64; B row ar; 16B chunk c
    int ar = tid >> 2, c = tid & 3;
    uint32_t a_soff  = (uint32_t)(ar * 64 + ((c ^ ((ar >> 1) & 3)) << 4));
    uint32_t a_soff2 = a_soff + 4096;                       // row+64, same swizzle
    uint32_t b_soff  = (uint32_t)(8192 + ar * 64 + ((c ^ ((ar >> 1) & 3)) << 4));
    long a_goff  = (long)(m0 + ar) * C_ + c * 8;
    long a_goff2 = a_goff + (long)64 * C_;
    long b_goff  = (long)(n0 + ar) * C_ + c * 8;

    // ---- ldmatrix address offsets (within stage) per (tile, k-step)
    uint32_t a_loff[2][2], b_loff[2][2];
#pragma unroll
    for (int mt = 0; mt < 2; mt++) {
        int row = warp_m * 32 + mt * 16 + (lane & 15);
        int sel = lane >> 4;
#pragma unroll
        for (int ks = 0; ks < 2; ks++) {
            int ch = 2 * ks + sel;
            a_loff[mt][ks] = (uint32_t)(row * 64 + ((ch ^ ((row >> 1) & 3)) << 4));
        }
    }
#pragma unroll
    for (int bt = 0; bt < 2; bt++) {
        int row = warp_n * 32 + bt * 16 + (lane & 15);
        int sel = lane >> 4;
#pragma unroll
        for (int ks = 0; ks < 2; ks++) {
            int ch = 2 * ks + sel;
            b_loff[bt][ks] = (uint32_t)(8192 + row * 64 + ((ch ^ ((row >> 1) & 3)) << 4));
        }
    }

    float acc[2][4][4];
#pragma unroll
    for (int i = 0; i < 2; i++)
#pragma unroll
        for (int j = 0; j < 4; j++)
#pragma unroll
            for (int q = 0; q < 4; q++) acc[i][j][q] = 0.f;

    // ---- stage loader
    auto load_stage = [&](int ci, int s) {
        int term = ci >> 6;
        long kin = (long)(ci & 63) * 32;
        const unsigned short* Asrc = (term < 2) ? g_ahi : g_alo;
        const unsigned short* Bsrc = (term == 1) ? g_blo : g_bhi;
        uint32_t sa = sbase + (uint32_t)s * STAGE_BYTES;
        cp16(sa + a_soff,  Asrc + a_goff  + kin);
        cp16(sa + a_soff2, Asrc + a_goff2 + kin);
        cp16(sa + b_soff,  Bsrc + b_goff  + kin);
        asm volatile("cp.async.commit_group;" ::: "memory");
    };

    load_stage(0, 0);
    load_stage(1, 1);
    load_stage(2, 2);

    for (int ci = 0; ci < NCHUNK; ci++) {
        asm volatile("cp.async.wait_group 2;" ::: "memory");
        __syncthreads();
        if (ci + 3 < NCHUNK) load_stage(ci + 3, (ci + 3) & 3);
        else asm volatile("cp.async.commit_group;" ::: "memory");

        uint32_t sa = sbase + (uint32_t)(ci & 3) * STAGE_BYTES;
#pragma unroll
        for (int ks = 0; ks < 2; ks++) {
            uint32_t af[2][4], bq[2][4];
            ldm4(af[0], sa + a_loff[0][ks]);
            ldm4(af[1], sa + a_loff[1][ks]);
            ldm4(bq[0], sa + b_loff[0][ks]);
            ldm4(bq[1], sa + b_loff[1][ks]);
#pragma unroll
            for (int mt = 0; mt < 2; mt++) {
                mma16816(acc[mt][0], af[mt], bq[0][0], bq[0][2]);
                mma16816(acc[mt][1], af[mt], bq[0][1], bq[0][3]);
                mma16816(acc[mt][2], af[mt], bq[1][0], bq[1][2]);
                mma16816(acc[mt][3], af[mt], bq[1][1], bq[1][3]);
            }
        }
    }

    // ---- epilogue
#pragma unroll
    for (int mt = 0; mt < 2; mt++) {
#pragma unroll
        for (int nt = 0; nt < 4; nt++) {
            int prow = m0 + warp_m * 32 + mt * 16 + (lane >> 2);
            int ncol = n0 + warp_n * 32 + nt * 8 + (lane & 3) * 2;
            if (prow < M_) {
                float2 v0 = make_float2(acc[mt][nt][0], acc[mt][nt][1]);
                *(float2*)(g_imgp + (long)prow * ID + ncol) = v0;
            }
            if (prow + 8 < M_) {
                float2 v1 = make_float2(acc[mt][nt][2], acc[mt][nt][3]);
                *(float2*)(g_imgp + (long)(prow + 8) * ID + ncol) = v1;
            }
        }
    }
}

// ---------------- K4: logits[p,n] = sum_d v[d]*tanh(imgp[p,d]*wordp[n,d]) ----------------
// 784 blocks: 2 pixels x half the classes each; MUFU tanh.approx
__global__ void __launch_bounds__(256) k_logits() {
    __shared__ float s_img[2 * ID];
    __shared__ float s_v[ID];
    int p0 = (blockIdx.x >> 1) * 2;
    int n0 = (blockIdx.x & 1) * 40;
    for (int e = threadIdx.x; e < 2 * ID; e += 256) s_img[e] = g_imgp[(long)p0 * ID + e];
    for (int e = threadIdx.x; e < ID; e += 256) s_v[e] = g_v[e];
    __syncthreads();
    int w = threadIdx.x >> 5, lane = threadIdx.x & 31;
    int b = p0 / HW_;
    int hw0 = p0 - b * HW_;
    for (int n = n0 + w; n < n0 + 40; n += 8) {
        const float* wrow = g_wordp + n * ID;
        float a0 = 0.f, a1 = 0.f;
#pragma unroll 4
        for (int d = lane; d < ID; d += 32) {
            float wv = wrow[d];
            float vv = s_v[d];
            float x0 = s_img[d] * wv;
            float x1 = s_img[ID + d] * wv;
            float t0, t1;
            asm("tanh.approx.f32 %0, %1;" : "=f"(t0) : "f"(x0));
            asm("tanh.approx.f32 %0, %1;" : "=f"(t1) : "f"(x1));
            a0 = fmaf(vv, t0, a0);
            a1 = fmaf(vv, t1, a1);
        }
#pragma unroll
        for (int off = 16; off; off >>= 1) {
            a0 += __shfl_xor_sync(~0u, a0, off);
            a1 += __shfl_xor_sync(~0u, a1, off);
        }
        if (lane == 0) {
            g_logits[(b * NCLS + n) * HW_ + hw0]     = a0;
            g_logits[(b * NCLS + n) * HW_ + hw0 + 1] = a1;
        }
    }
}

// ---------------- K5: softmax over the 196 spatial positions, per (b,n) row ----------------
__global__ void k_softmax() {
    int row = blockIdx.x;
    float* base = g_logits + row * HW_;
    int lane = threadIdx.x;
    float v[7];
    float mx = -1e30f;
#pragma unroll
    for (int i = 0; i < 7; i++) {
        int hw = lane + 32 * i;
        v[i] = (hw < HW_) ? base[hw] : -1e30f;
        mx = fmaxf(mx, v[i]);
    }
#pragma unroll
    for (int off = 16; off; off >>= 1) mx = fmaxf(mx, __shfl_xor_sync(~0u, mx, off));
    float sum = 0.f;
#pragma unroll
    for (int i = 0; i < 7; i++) {
        int hw = lane + 32 * i;
        float e = (hw < HW_) ? __expf(v[i] - mx) : 0.0f;
        v[i] = e;
        sum += e;
    }
#pragma unroll
    for (int off = 16; off; off >>= 1) sum += __shfl_xor_sync(~0u, sum, off);
    float inv = __fdividef(1.0f, sum);
#pragma unroll
    for (int i = 0; i < 7; i++) {
        int hw = lane + 32 * i;
        if (hw < HW_) base[hw] = v[i] * inv;
    }
}

// ---------------- K6: out[b,n,c] = sum_hw coef[b,n,hw] * img[b,c,hw] ----------------
__global__ void __launch_bounds__(256) k_pool(const float* __restrict__ img,
                                              float* __restrict__ out) {
    __shared__ float s_x[HW_ * 33];
    __shared__ float s_c[16 * HW_];
    int b  = blockIdx.y;
    int c0 = blockIdx.x * 32;
    for (int e = threadIdx.x; e < 32 * HW_; e += 256) {
        int cl = e / HW_, hw = e - cl * HW_;
        s_x[hw * 33 + cl] = img[(long)b * C_ * HW_ + (long)(c0 + cl) * HW_ + hw];
    }
    int cl = threadIdx.x & 31, np = threadIdx.x >> 5;
    for (int nc = 0; nc < NCLS; nc += 16) {
        __syncthreads();
        for (int e = threadIdx.x; e < 16 * HW_; e += 256) {
            int i = e / HW_, hw = e - i * HW_;
            s_c[e] = g_logits[(b * NCLS + nc + i) * HW_ + hw];
        }
        __syncthreads();
        const float* cp0 = s_c + (2 * np) * HW_;
        const float* cp1 = cp0 + HW_;
        float acc0 = 0.f, acc1 = 0.f;
#pragma unroll 4
        for (int hw = 0; hw < HW_; hw++) {
            float x = s_x[hw * 33 + cl];
            acc0 = fmaf(x, cp0[hw], acc0);
            acc1 = fmaf(x, cp1[hw], acc1);
        }
        int n = nc + 2 * np;
        out[((long)b * NCLS + n) * C_ + c0 + cl]     = acc0;
        out[((long)b * NCLS + n + 1) * C_ + c0 + cl] = acc1;
    }
}

// ---------------- launch ----------------
extern "C" void kernel_launch(void* const* d_in, const int* in_sizes, int n_in,
                              void* d_out, int out_size) {
    (void)in_sizes; (void)n_in; (void)out_size;
    const float* img  = (const float*)d_in[0];  // [B,C,H,W]
    const float* wf   = (const float*)d_in[1];  // [N,WD]
    const float* fc1w = (const float*)d_in[2];  // [ID,C]
    const float* fc2w = (const float*)d_in[3];  // [ID,WD]
    const float* fc3w = (const float*)d_in[4];  // [ID,ID]
    // d_in[5] fc3_b, d_in[7] fc4_b: constant over softmax axis -> cancel
    const float* fc4w = (const float*)d_in[6];  // [1,ID]
    float* out = (float*)d_out;                 // [B,N,C] fp32

    k_prep   <<<PREP_BLOCKS, 256>>>(img, wf, fc1w, fc2w, fc3w, fc4w);
    k_mma    <<<dim3(16, 7), 256>>>();
    k_logits <<<784, 256>>>();
    k_softmax<<<320, 32>>>();
    k_pool   <<<dim3(64, 4), 256>>>(img, out);
}

// round 5
// speedup vs baseline: 2.1450x; 2.1450x over previous
#include <cuda_runtime.h>
#include <cuda_bf16.h>
#include <cstdint>

#define B_   4
#define C_   2048
#define HW_  196
#define M_   784          // B_*HW_
#define MPAD 896          // 7*128
#define NCLS 80
#define WD   300
#define ID   1024

// ---------------- scratch (static device globals; no allocs) ----------------
__device__ float g_v[ID];                   // fc4_w @ fc3_w
__device__ float g_wordp[NCLS * ID];        // word_features @ fc2_w^T
__device__ float g_fc2t[WD * ID];           // fc2_w transposed: [k][d]
__device__ float g_imgp[M_ * ID];           // x @ fc1_w^T
__device__ float g_logits[B_ * NCLS * HW_]; // [b][n][hw], softmaxed in place
// bf16 hi/lo splits, K-major rows of 2048 (16B-aligned for cp.async)
__device__ __align__(16) unsigned short g_ahi[MPAD * C_];
__device__ __align__(16) unsigned short g_alo[MPAD * C_];
__device__ __align__(16) unsigned short g_bhi[ID * C_];
__device__ __align__(16) unsigned short g_blo[ID * C_];

__device__ __forceinline__ uint32_t smem_u32(const void* p) {
    return (uint32_t)__cvta_generic_to_shared(p);
}

// ---------------- K0a: split+transpose img -> a_hi/a_lo [p][c] bf16 ----------------
__global__ void __launch_bounds__(256) k_split_a(const float* __restrict__ img) {
    __shared__ float s[32 * 197];
    int b = blockIdx.y, c0 = blockIdx.x * 32;
    for (int e = threadIdx.x; e < 32 * HW_; e += 256) {
        int ci = e / HW_, hw = e - ci * HW_;
        s[ci * 197 + hw] = img[((long)b * C_ + c0 + ci) * HW_ + hw];
    }
    __syncthreads();
    int ci = threadIdx.x & 31, hw0 = threadIdx.x >> 5;
    for (int hw = hw0; hw < HW_; hw += 8) {
        float x = s[ci * 197 + hw];
        __nv_bfloat16 h = __float2bfloat16_rn(x);
        __nv_bfloat16 l = __float2bfloat16_rn(x - __bfloat162float(h));
        long o = (long)(b * HW_ + hw) * C_ + c0 + ci;
        g_ahi[o] = __bfloat16_as_ushort(h);
        g_alo[o] = __bfloat16_as_ushort(l);
    }
}

// ---------------- K0b: split fc1_w -> b_hi/b_lo [d][c] bf16 ----------------
__global__ void __launch_bounds__(256) k_split_b(const float* __restrict__ w) {
    int idx = blockIdx.x * 256 + threadIdx.x;   // float4 index, ID*C_/4 total
    float4 v = ((const float4*)w)[idx];
    float vv[4] = {v.x, v.y, v.z, v.w};
    unsigned h[4], l[4];
#pragma unroll
    for (int i = 0; i < 4; i++) {
        __nv_bfloat16 hh = __float2bfloat16_rn(vv[i]);
        __nv_bfloat16 ll = __float2bfloat16_rn(vv[i] - __bfloat162float(hh));
        h[i] = __bfloat16_as_ushort(hh);
        l[i] = __bfloat16_as_ushort(ll);
    }
    ((uint2*)g_bhi)[idx] = make_uint2(h[0] | (h[1] << 16), h[2] | (h[3] << 16));
    ((uint2*)g_blo)[idx] = make_uint2(l[0] | (l[1] << 16), l[2] | (l[3] << 16));
}

// ---------------- K1: v[d] = sum_e fc4_w[e] * fc3_w[e,d] ----------------
__global__ void k_v(const float* __restrict__ fc3_w, const float* __restrict__ fc4_w) {
    __shared__ float red[256];
    int d0 = blockIdx.x * 16;
    int dl = threadIdx.x & 15;
    int eg = threadIdx.x >> 4;
    int d  = d0 + dl;
    float acc = 0.f;
    int e0 = eg * 64;
#pragma unroll 8
    for (int e = e0; e < e0 + 64; e++)
        acc = fmaf(fc4_w[e], fc3_w[e * ID + d], acc);
    red[threadIdx.x] = acc;
    __syncthreads();
    if (threadIdx.x < 16) {
        float s = 0.f;
#pragma unroll
        for (int g = 0; g < 16; g++) s += red[g * 16 + threadIdx.x];
        g_v[d0 + threadIdx.x] = s;
    }
}

// ---------------- K2a: transpose fc2_w [ID][WD] -> g_fc2t [WD][ID] ----------------
__global__ void __launch_bounds__(256) k_t2(const float* __restrict__ fc2w) {
    __shared__ float t[32][33];
    int d0 = blockIdx.x * 32, k0 = blockIdx.y * 32;
    int tx = threadIdx.x & 31, ty = threadIdx.x >> 5;   // 32x8
#pragma unroll
    for (int i = 0; i < 4; i++) {
        int d = d0 + ty + i * 8, k = k0 + tx;
        t[ty + i * 8][tx] = (k < WD) ? fc2w[(long)d * WD + k] : 0.0f;
    }
    __syncthreads();
#pragma unroll
    for (int i = 0; i < 4; i++) {
        int k = k0 + ty + i * 8, d = d0 + tx;
        if (k < WD) g_fc2t[(long)k * ID + d] = t[tx][ty + i * 8];
    }
}

// ---------------- K2b: wordp[n,d] = sum_k wf[n,k] * fc2t[k,d] ----------------
// thread-per-output: lanes span d (coalesced fc2t), n warp-uniform (wf broadcast)
__global__ void __launch_bounds__(256) k_wordp(const float* __restrict__ wf) {
    int idx = blockIdx.x * 256 + threadIdx.x;   // 0 .. 81919
    int n = idx >> 10;
    int d = idx & 1023;
    const float* wrow = wf + n * WD;
    const float* col  = g_fc2t + d;
    float acc = 0.f;
#pragma unroll 4
    for (int k = 0; k < WD; k++)
        acc = fmaf(wrow[k], col[(long)k * ID], acc);
    g_wordp[n * ID + d] = acc;
}

// ---------------- K3: bf16 mma.sync GEMM, 3-term split as K=6144 ----------------
// block 128(M) x 64(N), 8 warps (4x2 of 32x32), K-chunk 32, 4-stage cp.async
#define STAGE_BYTES 12288     // A 128x32x2 = 8192, B 64x32x2 = 4096
#define NCHUNK 192            // 3 terms * 64 chunks

__device__ __forceinline__ void cp16(uint32_t s, const void* g) {
    asm volatile("cp.async.cg.shared.global [%0], [%1], 16;" :: "r"(s), "l"(g));
}
__device__ __forceinline__ void ldm4(uint32_t* r, uint32_t a) {
    asm volatile("ldmatrix.sync.aligned.m8n8.x4.shared.b16 {%0,%1,%2,%3}, [%4];"
                 : "=r"(r[0]), "=r"(r[1]), "=r"(r[2]), "=r"(r[3]) : "r"(a));
}
__device__ __forceinline__ void mma16816(float* c, const uint32_t* a, uint32_t b0, uint32_t b1) {
    asm volatile("mma.sync.aligned.m16n8k16.row.col.f32.bf16.bf16.f32 "
                 "{%0,%1,%2,%3}, {%4,%5,%6,%7}, {%8,%9}, {%0,%1,%2,%3};"
                 : "+f"(c[0]), "+f"(c[1]), "+f"(c[2]), "+f"(c[3])
                 : "r"(a[0]), "r"(a[1]), "r"(a[2]), "r"(a[3]), "r"(b0), "r"(b1));
}

__global__ void __launch_bounds__(256) k_mma() {
    __shared__ __align__(128) char smem[4][STAGE_BYTES];
    uint32_t sbase = smem_u32(smem);
    int tid = threadIdx.x;
    int lane = tid & 31, wid = tid >> 5;
    int warp_m = wid >> 1, warp_n = wid & 1;
    int m0 = blockIdx.y * 128, n0 = blockIdx.x * 64;

    // ---- loader mapping (per thread): A rows ar, ar+64; B row ar; 16B chunk c
    int ar = tid >> 2, c = tid & 3;
    uint32_t a_soff  = (uint32_t)(ar * 64 + ((c ^ ((ar >> 1) & 3)) << 4));
    uint32_t a_soff2 = a_soff + 4096;                       // row+64, same swizzle
    uint32_t b_soff  = (uint32_t)(8192 + ar * 64 + ((c ^ ((ar >> 1) & 3)) << 4));
    long a_goff  = (long)(m0 + ar) * C_ + c * 8;
    long a_goff2 = a_goff + (long)64 * C_;
    long b_goff  = (long)(n0 + ar) * C_ + c * 8;

    // ---- ldmatrix address offsets (within stage) per (tile, k-step)
    uint32_t a_loff[2][2], b_loff[2][2];
#pragma unroll
    for (int mt = 0; mt < 2; mt++) {
        int row = warp_m * 32 + mt * 16 + (lane & 15);
        int sel = lane >> 4;
#pragma unroll
        for (int ks = 0; ks < 2; ks++) {
            int ch = 2 * ks + sel;
            a_loff[mt][ks] = (uint32_t)(row * 64 + ((ch ^ ((row >> 1) & 3)) << 4));
        }
    }
#pragma unroll
    for (int bt = 0; bt < 2; bt++) {
        int row = warp_n * 32 + bt * 16 + (lane & 15);
        int sel = lane >> 4;
#pragma unroll
        for (int ks = 0; ks < 2; ks++) {
            int ch = 2 * ks + sel;
            b_loff[bt][ks] = (uint32_t)(8192 + row * 64 + ((ch ^ ((row >> 1) & 3)) << 4));
        }
    }

    float acc[2][4][4];
#pragma unroll
    for (int i = 0; i < 2; i++)
#pragma unroll
        for (int j = 0; j < 4; j++)
#pragma unroll
            for (int q = 0; q < 4; q++) acc[i][j][q] = 0.f;

    // ---- stage loader
    auto load_stage = [&](int ci, int s) {
        int term = ci >> 6;
        long kin = (long)(ci & 63) * 32;
        const unsigned short* Asrc = (term < 2) ? g_ahi : g_alo;
        const unsigned short* Bsrc = (term == 1) ? g_blo : g_bhi;
        uint32_t sa = sbase + (uint32_t)s * STAGE_BYTES;
        cp16(sa + a_soff,  Asrc + a_goff  + kin);
        cp16(sa + a_soff2, Asrc + a_goff2 + kin);
        cp16(sa + b_soff,  Bsrc + b_goff  + kin);
        asm volatile("cp.async.commit_group;" ::: "memory");
    };

    load_stage(0, 0);
    load_stage(1, 1);
    load_stage(2, 2);

    for (int ci = 0; ci < NCHUNK; ci++) {
        asm volatile("cp.async.wait_group 2;" ::: "memory");
        __syncthreads();
        if (ci + 3 < NCHUNK) load_stage(ci + 3, (ci + 3) & 3);
        else asm volatile("cp.async.commit_group;" ::: "memory");

        uint32_t sa = sbase + (uint32_t)(ci & 3) * STAGE_BYTES;
#pragma unroll
        for (int ks = 0; ks < 2; ks++) {
            uint32_t af[2][4], bq[2][4];
            ldm4(af[0], sa + a_loff[0][ks]);
            ldm4(af[1], sa + a_loff[1][ks]);
            ldm4(bq[0], sa + b_loff[0][ks]);
            ldm4(bq[1], sa + b_loff[1][ks]);
#pragma unroll
            for (int mt = 0; mt < 2; mt++) {
                mma16816(acc[mt][0], af[mt], bq[0][0], bq[0][2]);
                mma16816(acc[mt][1], af[mt], bq[0][1], bq[0][3]);
                mma16816(acc[mt][2], af[mt], bq[1][0], bq[1][2]);
                mma16816(acc[mt][3], af[mt], bq[1][1], bq[1][3]);
            }
        }
    }

    // ---- epilogue
#pragma unroll
    for (int mt = 0; mt < 2; mt++) {
#pragma unroll
        for (int nt = 0; nt < 4; nt++) {
            int prow = m0 + warp_m * 32 + mt * 16 + (lane >> 2);
            int ncol = n0 + warp_n * 32 + nt * 8 + (lane & 3) * 2;
            if (prow < M_) {
                float2 v0 = make_float2(acc[mt][nt][0], acc[mt][nt][1]);
                *(float2*)(g_imgp + (long)prow * ID + ncol) = v0;
            }
            if (prow + 8 < M_) {
                float2 v1 = make_float2(acc[mt][nt][2], acc[mt][nt][3]);
                *(float2*)(g_imgp + (long)(prow + 8) * ID + ncol) = v1;
            }
        }
    }
}

// ---------------- K4: logits[p,n] = sum_d v[d]*tanh(imgp[p,d]*wordp[n,d]) ----------------
// 784 blocks: 2 pixels x half the classes each; MUFU tanh.approx
__global__ void __launch_bounds__(256) k_logits() {
    __shared__ float s_img[2 * ID];
    __shared__ float s_v[ID];
    int p0 = (blockIdx.x >> 1) * 2;
    int n0 = (blockIdx.x & 1) * 40;
    for (int e = threadIdx.x; e < 2 * ID; e += 256) s_img[e] = g_imgp[(long)p0 * ID + e];
    for (int e = threadIdx.x; e < ID; e += 256) s_v[e] = g_v[e];
    __syncthreads();
    int w = threadIdx.x >> 5, lane = threadIdx.x & 31;
    int b = p0 / HW_;
    int hw0 = p0 - b * HW_;
    for (int n = n0 + w; n < n0 + 40; n += 8) {
        const float* wrow = g_wordp + n * ID;
        float a0 = 0.f, a1 = 0.f;
#pragma unroll 4
        for (int d = lane; d < ID; d += 32) {
            float wv = wrow[d];
            float vv = s_v[d];
            float x0 = s_img[d] * wv;
            float x1 = s_img[ID + d] * wv;
            float t0, t1;
            asm("tanh.approx.f32 %0, %1;" : "=f"(t0) : "f"(x0));
            asm("tanh.approx.f32 %0, %1;" : "=f"(t1) : "f"(x1));
            a0 = fmaf(vv, t0, a0);
            a1 = fmaf(vv, t1, a1);
        }
#pragma unroll
        for (int off = 16; off; off >>= 1) {
            a0 += __shfl_xor_sync(~0u, a0, off);
            a1 += __shfl_xor_sync(~0u, a1, off);
        }
        if (lane == 0) {
            g_logits[(b * NCLS + n) * HW_ + hw0]     = a0;
            g_logits[(b * NCLS + n) * HW_ + hw0 + 1] = a1;
        }
    }
}

// ---------------- K5: softmax over 196 spatial positions, warp-per-(b,n) row ----------------
__global__ void __launch_bounds__(256) k_softmax() {
    int row = blockIdx.x * 8 + (threadIdx.x >> 5);   // 40 blocks x 8 warps = 320 rows
    float* base = g_logits + row * HW_;
    int lane = threadIdx.x & 31;
    float v[7];
    float mx = -1e30f;
#pragma unroll
    for (int i = 0; i < 7; i++) {
        int hw = lane + 32 * i;
        v[i] = (hw < HW_) ? base[hw] : -1e30f;
        mx = fmaxf(mx, v[i]);
    }
#pragma unroll
    for (int off = 16; off; off >>= 1) mx = fmaxf(mx, __shfl_xor_sync(~0u, mx, off));
    float sum = 0.f;
#pragma unroll
    for (int i = 0; i < 7; i++) {
        int hw = lane + 32 * i;
        float e = (hw < HW_) ? __expf(v[i] - mx) : 0.0f;
        v[i] = e;
        sum += e;
    }
#pragma unroll
    for (int off = 16; off; off >>= 1) sum += __shfl_xor_sync(~0u, sum, off);
    float inv = __fdividef(1.0f, sum);
#pragma unroll
    for (int i = 0; i < 7; i++) {
        int hw = lane + 32 * i;
        if (hw < HW_) base[hw] = v[i] * inv;
    }
}

// ---------------- K6: out[b,n,c] = sum_hw coef[b,n,hw] * img[b,c,hw] ----------------
__global__ void __launch_bounds__(256) k_pool(const float* __restrict__ img,
                                              float* __restrict__ out) {
    __shared__ float s_x[HW_ * 33];
    __shared__ float s_c[16 * HW_];
    int b  = blockIdx.y;
    int c0 = blockIdx.x * 32;
    for (int e = threadIdx.x; e < 32 * HW_; e += 256) {
        int cl = e / HW_, hw = e - cl * HW_;
        s_x[hw * 33 + cl] = img[(long)b * C_ * HW_ + (long)(c0 + cl) * HW_ + hw];
    }
    int cl = threadIdx.x & 31, np = threadIdx.x >> 5;
    for (int nc = 0; nc < NCLS; nc += 16) {
        __syncthreads();
        for (int e = threadIdx.x; e < 16 * HW_; e += 256) {
            int i = e / HW_, hw = e - i * HW_;
            s_c[e] = g_logits[(b * NCLS + nc + i) * HW_ + hw];
        }
        __syncthreads();
        const float* cp0 = s_c + (2 * np) * HW_;
        const float* cp1 = cp0 + HW_;
        float acc0 = 0.f, acc1 = 0.f;
#pragma unroll 4
        for (int hw = 0; hw < HW_; hw++) {
            float x = s_x[hw * 33 + cl];
            acc0 = fmaf(x, cp0[hw], acc0);
            acc1 = fmaf(x, cp1[hw], acc1);
        }
        int n = nc + 2 * np;
        out[((long)b * NCLS + n) * C_ + c0 + cl]     = acc0;
        out[((long)b * NCLS + n + 1) * C_ + c0 + cl] = acc1;
    }
}

// ---------------- launch ----------------
extern "C" void kernel_launch(void* const* d_in, const int* in_sizes, int n_in,
                              void* d_out, int out_size) {
    (void)in_sizes; (void)n_in; (void)out_size;
    const float* img  = (const float*)d_in[0];  // [B,C,H,W]
    const float* wf   = (const float*)d_in[1];  // [N,WD]
    const float* fc1w = (const float*)d_in[2];  // [ID,C]
    const float* fc2w = (const float*)d_in[3];  // [ID,WD]
    const float* fc3w = (const float*)d_in[4];  // [ID,ID]
    // d_in[5] fc3_b, d_in[7] fc4_b: constant over softmax axis -> cancel
    const float* fc4w = (const float*)d_in[6];  // [1,ID]
    float* out = (float*)d_out;                 // [B,N,C] fp32

    k_split_a<<<dim3(64, 4), 256>>>(img);
    k_split_b<<<2048, 256>>>(fc1w);
    k_v      <<<64, 256>>>(fc3w, fc4w);
    k_t2     <<<dim3(32, 10), 256>>>(fc2w);
    k_wordp  <<<320, 256>>>(wf);
    k_mma    <<<dim3(16, 7), 256>>>();
    k_logits <<<784, 256>>>();
    k_softmax<<<40, 256>>>();
    k_pool   <<<dim3(64, 4), 256>>>(img, out);
}

// round 6
// speedup vs baseline: 2.8887x; 1.3467x over previous
#include <cuda_runtime.h>
#include <cuda_bf16.h>
#include <cstdint>

#define B_   4
#define C_   2048
#define HW_  196
#define M_   784          // B_*HW_
#define MPAD 896          // 7*128
#define NCLS 80
#define WD   300
#define ID   1024

// ---------------- scratch (static device globals; no allocs) ----------------
__device__ float g_v[ID];                   // fc4_w @ fc3_w
__device__ float g_wordp[NCLS * ID];        // word_features @ fc2_w^T
__device__ float g_imgpA[M_ * ID];          // x @ fc1_w^T  (K-split half 0)
__device__ float g_imgpB[M_ * ID];          // K-split half 1
__device__ float g_logits[B_ * NCLS * HW_]; // raw logits [b][n][hw]
// bf16 hi/lo splits, K-major rows of 2048 (16B-aligned for cp.async)
__device__ __align__(16) unsigned short g_ahi[MPAD * C_];
__device__ __align__(16) unsigned short g_alo[MPAD * C_];
__device__ __align__(16) unsigned short g_bhi[ID * C_];
__device__ __align__(16) unsigned short g_blo[ID * C_];

__device__ __forceinline__ uint32_t smem_u32(const void* p) {
    return (uint32_t)__cvta_generic_to_shared(p);
}

// ---------------- K_prep: fused split_a | split_b | v | wordp ----------------
// [0,256)      split+transpose img -> a_hi/a_lo
// [256,2304)   split fc1_w -> b_hi/b_lo
// [2304,2368)  v[d] = fc4_w @ fc3_w
// [2368,3648)  wordp: 128 d-tiles x 10 n-groups, fc2w tile in smem, warp-per-n
#define PREP_BLOCKS 3648

__global__ void __launch_bounds__(256) k_prep(const float* __restrict__ img,
                                              const float* __restrict__ wf,
                                              const float* __restrict__ fc1w,
                                              const float* __restrict__ fc2w,
                                              const float* __restrict__ fc3w,
                                              const float* __restrict__ fc4w) {
    __shared__ float s[32 * 197];   // 25.2KB union
    int bx = blockIdx.x;
    int tid = threadIdx.x;

    if (bx < 256) {
        // ---- split_a ----
        int b = bx >> 6, c0 = (bx & 63) * 32;
        for (int e = tid; e < 32 * HW_; e += 256) {
            int ci = e / HW_, hw = e - ci * HW_;
            s[ci * 197 + hw] = img[((long)b * C_ + c0 + ci) * HW_ + hw];
        }
        __syncthreads();
        int ci = tid & 31, hw0 = tid >> 5;
        for (int hw = hw0; hw < HW_; hw += 8) {
            float x = s[ci * 197 + hw];
            __nv_bfloat16 h = __float2bfloat16_rn(x);
            __nv_bfloat16 l = __float2bfloat16_rn(x - __bfloat162float(h));
            long o = (long)(b * HW_ + hw) * C_ + c0 + ci;
            g_ahi[o] = __bfloat16_as_ushort(h);
            g_alo[o] = __bfloat16_as_ushort(l);
        }
    } else if (bx < 2304) {
        // ---- split_b ----
        int idx = (bx - 256) * 256 + tid;    // float4 index
        float4 v = ((const float4*)fc1w)[idx];
        float vv[4] = {v.x, v.y, v.z, v.w};
        unsigned h[4], l[4];
#pragma unroll
        for (int i = 0; i < 4; i++) {
            __nv_bfloat16 hh = __float2bfloat16_rn(vv[i]);
            __nv_bfloat16 ll = __float2bfloat16_rn(vv[i] - __bfloat162float(hh));
            h[i] = __bfloat16_as_ushort(hh);
            l[i] = __bfloat16_as_ushort(ll);
        }
        ((uint2*)g_bhi)[idx] = make_uint2(h[0] | (h[1] << 16), h[2] | (h[3] << 16));
        ((uint2*)g_blo)[idx] = make_uint2(l[0] | (l[1] << 16), l[2] | (l[3] << 16));
    } else if (bx < 2368) {
        // ---- v ----
        int d0 = (bx - 2304) * 16;
        int dl = tid & 15, eg = tid >> 4;
        int d  = d0 + dl;
        float acc = 0.f;
        int e0 = eg * 64;
#pragma unroll 8
        for (int e = e0; e < e0 + 64; e++)
            acc = fmaf(fc4w[e], fc3w[e * ID + d], acc);
        s[tid] = acc;
        __syncthreads();
        if (tid < 16) {
            float sum = 0.f;
#pragma unroll
            for (int g = 0; g < 16; g++) sum += s[g * 16 + tid];
            g_v[d0 + tid] = sum;
        }
    } else {
        // ---- wordp: d-tile (8 rows of fc2w in smem) x n-group (8 n), warp-per-n
        int idx = bx - 2368;           // 0..1279
        int d0 = (idx & 127) * 8;
        int n  = (idx >> 7) * 8 + (tid >> 5);
        for (int e = tid; e < 8 * WD; e += 256) {
            int i = e / WD, k = e - i * WD;
            s[e] = fc2w[(long)(d0 + i) * WD + k];
        }
        __syncthreads();
        int lane = tid & 31;
        float acc[8] = {0, 0, 0, 0, 0, 0, 0, 0};
        const float* wrow = wf + n * WD;
        for (int k = lane; k < WD; k += 32) {
            float wv = wrow[k];
#pragma unroll
            for (int i = 0; i < 8; i++) acc[i] = fmaf(wv, s[i * WD + k], acc[i]);
        }
#pragma unroll
        for (int i = 0; i < 8; i++) {
#pragma unroll
            for (int off = 16; off; off >>= 1)
                acc[i] += __shfl_xor_sync(~0u, acc[i], off);
        }
        if (lane == 0) {
#pragma unroll
            for (int i = 0; i < 8; i++) g_wordp[n * ID + d0 + i] = acc[i];
        }
    }
}

// ---------------- K_mma: bf16 mma.sync, shared-tile 3-term, 128x128, K-split 2 ----
// stage = Ahi|Alo|Bhi|Blo, each 128 rows x 32 bf16 (64B) swizzled = 8KB -> 32KB/stage
#define STAGE_BYTES 32768
#define MMA_SMEM    (4 * STAGE_BYTES)   // 128KB dynamic
#define NCHUNK 32                       // K=1024 per CTA, chunks of 32

__device__ __forceinline__ void cp16(uint32_t s, const void* g) {
    asm volatile("cp.async.cg.shared.global [%0], [%1], 16;" :: "r"(s), "l"(g));
}
__device__ __forceinline__ void ldm4(uint32_t* r, uint32_t a) {
    asm volatile("ldmatrix.sync.aligned.m8n8.x4.shared.b16 {%0,%1,%2,%3}, [%4];"
                 : "=r"(r[0]), "=r"(r[1]), "=r"(r[2]), "=r"(r[3]) : "r"(a));
}
__device__ __forceinline__ void mma16816(float* c, const uint32_t* a, uint32_t b0, uint32_t b1) {
    asm volatile("mma.sync.aligned.m16n8k16.row.col.f32.bf16.bf16.f32 "
                 "{%0,%1,%2,%3}, {%4,%5,%6,%7}, {%8,%9}, {%0,%1,%2,%3};"
                 : "+f"(c[0]), "+f"(c[1]), "+f"(c[2]), "+f"(c[3])
                 : "r"(a[0]), "r"(a[1]), "r"(a[2]), "r"(a[3]), "r"(b0), "r"(b1));
}
#define SWZ64(row, ch) ((uint32_t)((row) * 64 + (((ch) ^ (((row) >> 1) & 3)) << 4)))

__global__ void __launch_bounds__(256) k_mma() {
    extern __shared__ __align__(128) char smem[];
    uint32_t sbase = smem_u32(smem);
    int tid = threadIdx.x;
    int lane = tid & 31, wid = tid >> 5;
    int warp_m = wid >> 1, warp_n = wid & 1;        // 4 x 2 warps, warp 32M x 64N
    int m0 = blockIdx.y * 128, n0 = blockIdx.x * 128;
    long kz = (long)blockIdx.z * 1024;

    // ---- loader mapping: each thread: rows r, r+64 of each of 4 tiles, chunk c
    int lr = tid >> 2, c = tid & 3;
    uint32_t soff  = SWZ64(lr, c);           // rows 0..63
    uint32_t soff2 = SWZ64(lr + 64, c);      // rows 64..127
    long aGr  = (long)(m0 + lr) * C_ + kz + c * 8;
    long aGr2 = aGr + (long)64 * C_;
    long bGr  = (long)(n0 + lr) * C_ + kz + c * 8;
    long bGr2 = bGr + (long)64 * C_;

    auto load_stage = [&](int ci, int st) {
        uint32_t sa = sbase + (uint32_t)st * STAGE_BYTES;
        long ko = (long)ci * 32;
        cp16(sa + soff,          g_ahi + aGr  + ko);
        cp16(sa + soff2,         g_ahi + aGr2 + ko);
        cp16(sa + 8192  + soff,  g_alo + aGr  + ko);
        cp16(sa + 8192  + soff2, g_alo + aGr2 + ko);
        cp16(sa + 16384 + soff,  g_bhi + bGr  + ko);
        cp16(sa + 16384 + soff2, g_bhi + bGr2 + ko);
        cp16(sa + 24576 + soff,  g_blo + bGr  + ko);
        cp16(sa + 24576 + soff2, g_blo + bGr2 + ko);
        asm volatile("cp.async.commit_group;" ::: "memory");
    };

    // ---- fragment smem offsets (within stage), per (mt|bt, ks)
    int sel = lane >> 4;
    uint32_t a_off[2][2], b_off[4][2];
#pragma unroll
    for (int mt = 0; mt < 2; mt++) {
        int row = warp_m * 32 + mt * 16 + (lane & 15);
#pragma unroll
        for (int ks = 0; ks < 2; ks++)
            a_off[mt][ks] = SWZ64(row, 2 * ks + sel);
    }
#pragma unroll
    for (int bt = 0; bt < 4; bt++) {
        int row = warp_n * 64 + bt * 16 + (lane & 15);
#pragma unroll
        for (int ks = 0; ks < 2; ks++)
            b_off[bt][ks] = SWZ64(row, 2 * ks + sel);
    }

    float acc[2][8][4];
#pragma unroll
    for (int i = 0; i < 2; i++)
#pragma unroll
        for (int j = 0; j < 8; j++)
#pragma unroll
            for (int q = 0; q < 4; q++) acc[i][j][q] = 0.f;

    load_stage(0, 0);
    load_stage(1, 1);
    load_stage(2, 2);

    for (int ci = 0; ci < NCHUNK; ci++) {
        asm volatile("cp.async.wait_group 2;" ::: "memory");
        __syncthreads();
        if (ci + 3 < NCHUNK) load_stage(ci + 3, (ci + 3) & 3);
        else asm volatile("cp.async.commit_group;" ::: "memory");

        uint32_t sa = sbase + (uint32_t)(ci & 3) * STAGE_BYTES;
#pragma unroll
        for (int ks = 0; ks < 2; ks++) {
            uint32_t ahi[2][4], alo[2][4], bhi[4][4], blo[4][4];
#pragma unroll
            for (int mt = 0; mt < 2; mt++) {
                ldm4(ahi[mt], sa + a_off[mt][ks]);
                ldm4(alo[mt], sa + 8192 + a_off[mt][ks]);
            }
#pragma unroll
            for (int bt = 0; bt < 4; bt++) {
                ldm4(bhi[bt], sa + 16384 + b_off[bt][ks]);
                ldm4(blo[bt], sa + 24576 + b_off[bt][ks]);
            }
#pragma unroll
            for (int mt = 0; mt < 2; mt++) {
#pragma unroll
                for (int bt = 0; bt < 4; bt++) {
                    // term 0: Ahi*Bhi
                    mma16816(acc[mt][2 * bt],     ahi[mt], bhi[bt][0], bhi[bt][2]);
                    mma16816(acc[mt][2 * bt + 1], ahi[mt], bhi[bt][1], bhi[bt][3]);
                    // term 1: Ahi*Blo
                    mma16816(acc[mt][2 * bt],     ahi[mt], blo[bt][0], blo[bt][2]);
                    mma16816(acc[mt][2 * bt + 1], ahi[mt], blo[bt][1], blo[bt][3]);
                    // term 2: Alo*Bhi
                    mma16816(acc[mt][2 * bt],     alo[mt], bhi[bt][0], bhi[bt][2]);
                    mma16816(acc[mt][2 * bt + 1], alo[mt], bhi[bt][1], bhi[bt][3]);
                }
            }
        }
    }

    // ---- epilogue: write K-split half to its buffer
    float* outb = blockIdx.z ? g_imgpB : g_imgpA;
#pragma unroll
    for (int mt = 0; mt < 2; mt++) {
#pragma unroll
        for (int nt = 0; nt < 8; nt++) {
            int prow = m0 + warp_m * 32 + mt * 16 + (lane >> 2);
            int ncol = n0 + warp_n * 64 + nt * 8 + (lane & 3) * 2;
            if (prow < M_)
                *(float2*)(outb + (long)prow * ID + ncol) =
                    make_float2(acc[mt][nt][0], acc[mt][nt][1]);
            if (prow + 8 < M_)
                *(float2*)(outb + (long)(prow + 8) * ID + ncol) =
                    make_float2(acc[mt][nt][2], acc[mt][nt][3]);
        }
    }
}

// ---------------- K_logits: logits[p,n] = sum_d v[d]*tanh(imgp[p,d]*wordp[n,d]) ----
__global__ void __launch_bounds__(256) k_logits() {
    __shared__ float s_img[2 * ID];
    __shared__ float s_v[ID];
    int p0 = (blockIdx.x >> 1) * 2;
    int n0 = (blockIdx.x & 1) * 40;
    for (int e = threadIdx.x; e < 2 * ID; e += 256) {
        long o = (long)p0 * ID + e;
        s_img[e] = g_imgpA[o] + g_imgpB[o];
    }
    for (int e = threadIdx.x; e < ID; e += 256) s_v[e] = g_v[e];
    __syncthreads();
    int w = threadIdx.x >> 5, lane = threadIdx.x & 31;
    int b = p0 / HW_;
    int hw0 = p0 - b * HW_;
    for (int n = n0 + w; n < n0 + 40; n += 8) {
        const float* wrow = g_wordp + n * ID;
        float a0 = 0.f, a1 = 0.f;
#pragma unroll 4
        for (int d = lane; d < ID; d += 32) {
            float wv = wrow[d];
            float vv = s_v[d];
            float x0 = s_img[d] * wv;
            float x1 = s_img[ID + d] * wv;
            float t0, t1;
            asm("tanh.approx.f32 %0, %1;" : "=f"(t0) : "f"(x0));
            asm("tanh.approx.f32 %0, %1;" : "=f"(t1) : "f"(x1));
            a0 = fmaf(vv, t0, a0);
            a1 = fmaf(vv, t1, a1);
        }
#pragma unroll
        for (int off = 16; off; off >>= 1) {
            a0 += __shfl_xor_sync(~0u, a0, off);
            a1 += __shfl_xor_sync(~0u, a1, off);
        }
        if (lane == 0) {
            g_logits[(b * NCLS + n) * HW_ + hw0]     = a0;
            g_logits[(b * NCLS + n) * HW_ + hw0 + 1] = a1;
        }
    }
}

// ---------------- K_pool: inline softmax + out[b,n,c] = sum_hw coef * x ----------------
__global__ void __launch_bounds__(256) k_pool(const float* __restrict__ img,
                                              float* __restrict__ out) {
    __shared__ float s_x[HW_ * 33];
    __shared__ float s_c[16 * HW_];
    int b  = blockIdx.y;
    int c0 = blockIdx.x * 32;
    int tid = threadIdx.x;
    for (int e = tid; e < 32 * HW_; e += 256) {
        int cl = e / HW_, hw = e - cl * HW_;
        s_x[hw * 33 + cl] = img[(long)b * C_ * HW_ + (long)(c0 + cl) * HW_ + hw];
    }
    int cl = tid & 31, np = tid >> 5;
    for (int nc = 0; nc < NCLS; nc += 16) {
        __syncthreads();
        for (int e = tid; e < 16 * HW_; e += 256) {
            int i = e / HW_, hw = e - i * HW_;
            s_c[e] = g_logits[(b * NCLS + nc + i) * HW_ + hw];
        }
        __syncthreads();
        // inline softmax over each of the 16 rows (warp w -> rows w, w+8)
        {
            int w = tid >> 5, lane = tid & 31;
            for (int r = w; r < 16; r += 8) {
                float* row = s_c + r * HW_;
                float v[7];
                float mx = -1e30f;
#pragma unroll
                for (int i = 0; i < 7; i++) {
                    int hw = lane + 32 * i;
                    v[i] = (hw < HW_) ? row[hw] : -1e30f;
                    mx = fmaxf(mx, v[i]);
                }
#pragma unroll
                for (int off = 16; off; off >>= 1)
                    mx = fmaxf(mx, __shfl_xor_sync(~0u, mx, off));
                float sum = 0.f;
#pragma unroll
                for (int i = 0; i < 7; i++) {
                    int hw = lane + 32 * i;
                    float e = (hw < HW_) ? __expf(v[i] - mx) : 0.0f;
                    v[i] = e;
                    sum += e;
                }
#pragma unroll
                for (int off = 16; off; off >>= 1)
                    sum += __shfl_xor_sync(~0u, sum, off);
                float inv = __fdividef(1.0f, sum);
#pragma unroll
                for (int i = 0; i < 7; i++) {
                    int hw = lane + 32 * i;
                    if (hw < HW_) row[hw] = v[i] * inv;
                }
            }
        }
        __syncthreads();
        const float* cp0 = s_c + (2 * np) * HW_;
        const float* cp1 = cp0 + HW_;
        float acc0 = 0.f, acc1 = 0.f;
#pragma unroll 4
        for (int hw = 0; hw < HW_; hw++) {
            float x = s_x[hw * 33 + cl];
            acc0 = fmaf(x, cp0[hw], acc0);
            acc1 = fmaf(x, cp1[hw], acc1);
        }
        int n = nc + 2 * np;
        out[((long)b * NCLS + n) * C_ + c0 + cl]     = acc0;
        out[((long)b * NCLS + n + 1) * C_ + c0 + cl] = acc1;
    }
}

// ---------------- launch ----------------
extern "C" void kernel_launch(void* const* d_in, const int* in_sizes, int n_in,
                              void* d_out, int out_size) {
    (void)in_sizes; (void)n_in; (void)out_size;
    const float* img  = (const float*)d_in[0];  // [B,C,H,W]
    const float* wf   = (const float*)d_in[1];  // [N,WD]
    const float* fc1w = (const float*)d_in[2];  // [ID,C]
    const float* fc2w = (const float*)d_in[3];  // [ID,WD]
    const float* fc3w = (const float*)d_in[4];  // [ID,ID]
    // d_in[5] fc3_b, d_in[7] fc4_b: constant over softmax axis -> cancel
    const float* fc4w = (const float*)d_in[6];  // [1,ID]
    float* out = (float*)d_out;                 // [B,N,C] fp32

    cudaFuncSetAttribute(k_mma, cudaFuncAttributeMaxDynamicSharedMemorySize, MMA_SMEM);

    k_prep  <<<PREP_BLOCKS, 256>>>(img, wf, fc1w, fc2w, fc3w, fc4w);
    k_mma   <<<dim3(8, 7, 2), 256, MMA_SMEM>>>();
    k_logits<<<784, 256>>>();
    k_pool  <<<dim3(64, 4), 256>>>(img, out);
}

// round 8
// speedup vs baseline: 3.1506x; 1.0907x over previous
#include <cuda_runtime.h>
#include <cuda_bf16.h>
#include <cstdint>

#define B_   4
#define C_   2048
#define HW_  196
#define M_   784          // B_*HW_
#define MPAD 896          // 7*128
#define NCLS 80
#define WD   300
#define ID   1024

// ---------------- scratch (static device globals; no allocs) ----------------
__device__ float g_v[ID];                   // fc4_w @ fc3_w
__device__ float g_wordp[NCLS * ID];        // word_features @ fc2_w^T
__device__ float g_imgpA[M_ * ID];          // x @ fc1_w^T  (K-split half 0)
__device__ float g_imgpB[M_ * ID];          // K-split half 1
__device__ float g_logits[B_ * NCLS * HW_]; // [b][n][hw], softmaxed in place
// bf16 hi/lo splits, K-major rows of 2048 (16B-aligned for cp.async)
__device__ __align__(16) unsigned short g_ahi[MPAD * C_];
__device__ __align__(16) unsigned short g_alo[MPAD * C_];
__device__ __align__(16) unsigned short g_bhi[ID * C_];
__device__ __align__(16) unsigned short g_blo[ID * C_];

__device__ __forceinline__ uint32_t smem_u32(const void* p) {
    return (uint32_t)__cvta_generic_to_shared(p);
}

// ---------------- K_prep: fused split_a | split_b | v | wordp ----------------
#define PREP_BLOCKS 3648

__global__ void __launch_bounds__(256) k_prep(const float* __restrict__ img,
                                              const float* __restrict__ wf,
                                              const float* __restrict__ fc1w,
                                              const float* __restrict__ fc2w,
                                              const float* __restrict__ fc3w,
                                              const float* __restrict__ fc4w) {
    __shared__ float s[32 * 197];   // 25.2KB union
    int bx = blockIdx.x;
    int tid = threadIdx.x;

    if (bx < 256) {
        // ---- split_a ----
        int b = bx >> 6, c0 = (bx & 63) * 32;
        for (int e = tid; e < 32 * HW_; e += 256) {
            int ci = e / HW_, hw = e - ci * HW_;
            s[ci * 197 + hw] = img[((long)b * C_ + c0 + ci) * HW_ + hw];
        }
        __syncthreads();
        int ci = tid & 31, hw0 = tid >> 5;
        for (int hw = hw0; hw < HW_; hw += 8) {
            float x = s[ci * 197 + hw];
            __nv_bfloat16 h = __float2bfloat16_rn(x);
            __nv_bfloat16 l = __float2bfloat16_rn(x - __bfloat162float(h));
            long o = (long)(b * HW_ + hw) * C_ + c0 + ci;
            g_ahi[o] = __bfloat16_as_ushort(h);
            g_alo[o] = __bfloat16_as_ushort(l);
        }
    } else if (bx < 2304) {
        // ---- split_b ----
        int idx = (bx - 256) * 256 + tid;    // float4 index
        float4 v = ((const float4*)fc1w)[idx];
        float vv[4] = {v.x, v.y, v.z, v.w};
        unsigned h[4], l[4];
#pragma unroll
        for (int i = 0; i < 4; i++) {
            __nv_bfloat16 hh = __float2bfloat16_rn(vv[i]);
            __nv_bfloat16 ll = __float2bfloat16_rn(vv[i] - __bfloat162float(hh));
            h[i] = __bfloat16_as_ushort(hh);
            l[i] = __bfloat16_as_ushort(ll);
        }
        ((uint2*)g_bhi)[idx] = make_uint2(h[0] | (h[1] << 16), h[2] | (h[3] << 16));
        ((uint2*)g_blo)[idx] = make_uint2(l[0] | (l[1] << 16), l[2] | (l[3] << 16));
    } else if (bx < 2368) {
        // ---- v ----
        int d0 = (bx - 2304) * 16;
        int dl = tid & 15, eg = tid >> 4;
        int d  = d0 + dl;
        float acc = 0.f;
        int e0 = eg * 64;
#pragma unroll 8
        for (int e = e0; e < e0 + 64; e++)
            acc = fmaf(fc4w[e], fc3w[e * ID + d], acc);
        s[tid] = acc;
        __syncthreads();
        if (tid < 16) {
            float sum = 0.f;
#pragma unroll
            for (int g = 0; g < 16; g++) sum += s[g * 16 + tid];
            g_v[d0 + tid] = sum;
        }
    } else {
        // ---- wordp: d-tile (8 rows of fc2w in smem) x n-group (8 n), warp-per-n
        int idx = bx - 2368;           // 0..1279
        int d0 = (idx & 127) * 8;
        int n  = (idx >> 7) * 8 + (tid >> 5);
        for (int e = tid; e < 8 * WD; e += 256) {
            int i = e / WD, k = e - i * WD;
            s[e] = fc2w[(long)(d0 + i) * WD + k];
        }
        __syncthreads();
        int lane = tid & 31;
        float acc[8] = {0, 0, 0, 0, 0, 0, 0, 0};
        const float* wrow = wf + n * WD;
        for (int k = lane; k < WD; k += 32) {
            float wv = wrow[k];
#pragma unroll
            for (int i = 0; i < 8; i++) acc[i] = fmaf(wv, s[i * WD + k], acc[i]);
        }
#pragma unroll
        for (int i = 0; i < 8; i++) {
#pragma unroll
            for (int off = 16; off; off >>= 1)
                acc[i] += __shfl_xor_sync(~0u, acc[i], off);
        }
        if (lane == 0) {
#pragma unroll
            for (int i = 0; i < 8; i++) g_wordp[n * ID + d0 + i] = acc[i];
        }
    }
}

// ---------------- K_mma: bf16 mma.sync, shared-tile 3-term, 128x128, K-split 2 ----
#define STAGE_BYTES 32768
#define MMA_SMEM    (4 * STAGE_BYTES)   // 128KB dynamic
#define NCHUNK 32                       // K=1024 per CTA, chunks of 32

__device__ __forceinline__ void cp16(uint32_t s, const void* g) {
    asm volatile("cp.async.cg.shared.global [%0], [%1], 16;" :: "r"(s), "l"(g));
}
__device__ __forceinline__ void ldm4(uint32_t* r, uint32_t a) {
    asm volatile("ldmatrix.sync.aligned.m8n8.x4.shared.b16 {%0,%1,%2,%3}, [%4];"
                 : "=r"(r[0]), "=r"(r[1]), "=r"(r[2]), "=r"(r[3]) : "r"(a));
}
__device__ __forceinline__ void mma16816(float* c, const uint32_t* a, uint32_t b0, uint32_t b1) {
    asm volatile("mma.sync.aligned.m16n8k16.row.col.f32.bf16.bf16.f32 "
                 "{%0,%1,%2,%3}, {%4,%5,%6,%7}, {%8,%9}, {%0,%1,%2,%3};"
                 : "+f"(c[0]), "+f"(c[1]), "+f"(c[2]), "+f"(c[3])
                 : "r"(a[0]), "r"(a[1]), "r"(a[2]), "r"(a[3]), "r"(b0), "r"(b1));
}
#define SWZ64(row, ch) ((uint32_t)((row) * 64 + (((ch) ^ (((row) >> 1) & 3)) << 4)))

__global__ void __launch_bounds__(256) k_mma() {
    extern __shared__ __align__(128) char smem[];
    uint32_t sbase = smem_u32(smem);
    int tid = threadIdx.x;
    int lane = tid & 31, wid = tid >> 5;
    int warp_m = wid >> 1, warp_n = wid & 1;        // 4 x 2 warps, warp 32M x 64N
    int m0 = blockIdx.y * 128, n0 = blockIdx.x * 128;
    long kz = (long)blockIdx.z * 1024;

    int lr = tid >> 2, c = tid & 3;
    uint32_t soff  = SWZ64(lr, c);
    uint32_t soff2 = SWZ64(lr + 64, c);
    long aGr  = (long)(m0 + lr) * C_ + kz + c * 8;
    long aGr2 = aGr + (long)64 * C_;
    long bGr  = (long)(n0 + lr) * C_ + kz + c * 8;
    long bGr2 = bGr + (long)64 * C_;

    auto load_stage = [&](int ci, int st) {
        uint32_t sa = sbase + (uint32_t)st * STAGE_BYTES;
        long ko = (long)ci * 32;
        cp16(sa + soff,          g_ahi + aGr  + ko);
        cp16(sa + soff2,         g_ahi + aGr2 + ko);
        cp16(sa + 8192  + soff,  g_alo + aGr  + ko);
        cp16(sa + 8192  + soff2, g_alo + aGr2 + ko);
        cp16(sa + 16384 + soff,  g_bhi + bGr  + ko);
        cp16(sa + 16384 + soff2, g_bhi + bGr2 + ko);
        cp16(sa + 24576 + soff,  g_blo + bGr  + ko);
        cp16(sa + 24576 + soff2, g_blo + bGr2 + ko);
        asm volatile("cp.async.commit_group;" ::: "memory");
    };

    int sel = lane >> 4;
    uint32_t a_off[2][2], b_off[4][2];
#pragma unroll
    for (int mt = 0; mt < 2; mt++) {
        int row = warp_m * 32 + mt * 16 + (lane & 15);
#pragma unroll
        for (int ks = 0; ks < 2; ks++)
            a_off[mt][ks] = SWZ64(row, 2 * ks + sel);
    }
#pragma unroll
    for (int bt = 0; bt < 4; bt++) {
        int row = warp_n * 64 + bt * 16 + (lane & 15);
#pragma unroll
        for (int ks = 0; ks < 2; ks++)
            b_off[bt][ks] = SWZ64(row, 2 * ks + sel);
    }

    float acc[2][8][4];
#pragma unroll
    for (int i = 0; i < 2; i++)
#pragma unroll
        for (int j = 0; j < 8; j++)
#pragma unroll
            for (int q = 0; q < 4; q++) acc[i][j][q] = 0.f;

    load_stage(0, 0);
    load_stage(1, 1);
    load_stage(2, 2);

    for (int ci = 0; ci < NCHUNK; ci++) {
        asm volatile("cp.async.wait_group 2;" ::: "memory");
        __syncthreads();
        if (ci + 3 < NCHUNK) load_stage(ci + 3, (ci + 3) & 3);
        else asm volatile("cp.async.commit_group;" ::: "memory");

        uint32_t sa = sbase + (uint32_t)(ci & 3) * STAGE_BYTES;
#pragma unroll
        for (int ks = 0; ks < 2; ks++) {
            uint32_t ahi[2][4], alo[2][4], bhi[4][4], blo[4][4];
#pragma unroll
            for (int mt = 0; mt < 2; mt++) {
                ldm4(ahi[mt], sa + a_off[mt][ks]);
                ldm4(alo[mt], sa + 8192 + a_off[mt][ks]);
            }
#pragma unroll
            for (int bt = 0; bt < 4; bt++) {
                ldm4(bhi[bt], sa + 16384 + b_off[bt][ks]);
                ldm4(blo[bt], sa + 24576 + b_off[bt][ks]);
            }
#pragma unroll
            for (int mt = 0; mt < 2; mt++) {
#pragma unroll
                for (int bt = 0; bt < 4; bt++) {
                    mma16816(acc[mt][2 * bt],     ahi[mt], bhi[bt][0], bhi[bt][2]);
                    mma16816(acc[mt][2 * bt + 1], ahi[mt], bhi[bt][1], bhi[bt][3]);
                    mma16816(acc[mt][2 * bt],     ahi[mt], blo[bt][0], blo[bt][2]);
                    mma16816(acc[mt][2 * bt + 1], ahi[mt], blo[bt][1], blo[bt][3]);
                    mma16816(acc[mt][2 * bt],     alo[mt], bhi[bt][0], bhi[bt][2]);
                    mma16816(acc[mt][2 * bt + 1], alo[mt], bhi[bt][1], bhi[bt][3]);
                }
            }
        }
    }

    float* outb = blockIdx.z ? g_imgpB : g_imgpA;
#pragma unroll
    for (int mt = 0; mt < 2; mt++) {
#pragma unroll
        for (int nt = 0; nt < 8; nt++) {
            int prow = m0 + warp_m * 32 + mt * 16 + (lane >> 2);
            int ncol = n0 + warp_n * 64 + nt * 8 + (lane & 3) * 2;
            if (prow < M_)
                *(float2*)(outb + (long)prow * ID + ncol) =
                    make_float2(acc[mt][nt][0], acc[mt][nt][1]);
            if (prow + 8 < M_)
                *(float2*)(outb + (long)(prow + 8) * ID + ncol) =
                    make_float2(acc[mt][nt][2], acc[mt][nt][3]);
        }
    }
}

// ---------------- K_logits: 4 pixels x 40 classes per block (392 blocks) ----------------
__global__ void __launch_bounds__(256) k_logits() {
    __shared__ float s_img[4 * ID];
    __shared__ float s_v[ID];
    int p0 = (blockIdx.x >> 1) * 4;
    int n0 = (blockIdx.x & 1) * 40;
    for (int e = threadIdx.x; e < 4 * ID; e += 256) {
        long o = (long)p0 * ID + e;
        s_img[e] = g_imgpA[o] + g_imgpB[o];
    }
    for (int e = threadIdx.x; e < ID; e += 256) s_v[e] = g_v[e];
    __syncthreads();
    int w = threadIdx.x >> 5, lane = threadIdx.x & 31;
    int b = p0 / HW_;                  // 4 | 196 so no straddle
    int hw0 = p0 - b * HW_;
    for (int n = n0 + w; n < n0 + 40; n += 8) {
        const float* wrow = g_wordp + n * ID;
        float a0 = 0.f, a1 = 0.f, a2 = 0.f, a3 = 0.f;
#pragma unroll 4
        for (int d = lane; d < ID; d += 32) {
            float wv = wrow[d];
            float vv = s_v[d];
            float t0, t1, t2, t3;
            float x0 = s_img[d] * wv;
            float x1 = s_img[ID + d] * wv;
            float x2 = s_img[2 * ID + d] * wv;
            float x3 = s_img[3 * ID + d] * wv;
            asm("tanh.approx.f32 %0, %1;" : "=f"(t0) : "f"(x0));
            asm("tanh.approx.f32 %0, %1;" : "=f"(t1) : "f"(x1));
            asm("tanh.approx.f32 %0, %1;" : "=f"(t2) : "f"(x2));
            asm("tanh.approx.f32 %0, %1;" : "=f"(t3) : "f"(x3));
            a0 = fmaf(vv, t0, a0);
            a1 = fmaf(vv, t1, a1);
            a2 = fmaf(vv, t2, a2);
            a3 = fmaf(vv, t3, a3);
        }
#pragma unroll
        for (int off = 16; off; off >>= 1) {
            a0 += __shfl_xor_sync(~0u, a0, off);
            a1 += __shfl_xor_sync(~0u, a1, off);
            a2 += __shfl_xor_sync(~0u, a2, off);
            a3 += __shfl_xor_sync(~0u, a3, off);
        }
        if (lane == 0) {
            float* dst = g_logits + (b * NCLS + n) * HW_ + hw0;
            dst[0] = a0; dst[1] = a1; dst[2] = a2; dst[3] = a3;
        }
    }
}

// ---------------- K_softmax: warp-per-(b,n) row over 196 positions ----------------
__global__ void __launch_bounds__(256) k_softmax() {
    int row = blockIdx.x * 8 + (threadIdx.x >> 5);   // 40 blocks x 8 warps = 320 rows
    float* base = g_logits + row * HW_;
    int lane = threadIdx.x & 31;
    float v[7];
    float mx = -1e30f;
#pragma unroll
    for (int i = 0; i < 7; i++) {
        int hw = lane + 32 * i;
        v[i] = (hw < HW_) ? base[hw] : -1e30f;
        mx = fmaxf(mx, v[i]);
    }
#pragma unroll
    for (int off = 16; off; off >>= 1) mx = fmaxf(mx, __shfl_xor_sync(~0u, mx, off));
    float sum = 0.f;
#pragma unroll
    for (int i = 0; i < 7; i++) {
        int hw = lane + 32 * i;
        float e = (hw < HW_) ? __expf(v[i] - mx) : 0.0f;
        v[i] = e;
        sum += e;
    }
#pragma unroll
    for (int off = 16; off; off >>= 1) sum += __shfl_xor_sync(~0u, sum, off);
    float inv = __fdividef(1.0f, sum);
#pragma unroll
    for (int i = 0; i < 7; i++) {
        int hw = lane + 32 * i;
        if (hw < HW_) base[hw] = v[i] * inv;
    }
}

// ---------------- K_pool: out[b,n,c] = sum_hw coef[b,n,hw] * x[b,hw,c] ----------------
// dynamic smem: s_x[32][196] + s_c[80][196]; float4 inner loop, 10 n-acc per thread
#define POOL_SMEM ((32 * HW_ + NCLS * HW_) * 4)   // 87.8KB

__global__ void __launch_bounds__(256) k_pool(const float* __restrict__ img,
                                              float* __restrict__ out) {
    extern __shared__ __align__(16) float sp[];
    float* s_x = sp;                 // [32][196]
    float* s_c = sp + 32 * HW_;      // [80][196]
    int b  = blockIdx.y;
    int c0 = blockIdx.x * 32;
    int tid = threadIdx.x;
    for (int e = tid; e < 32 * HW_; e += 256) {
        int cl = e / HW_, hw = e - cl * HW_;
        s_x[cl * HW_ + hw] = img[(long)b * C_ * HW_ + (long)(c0 + cl) * HW_ + hw];
    }
    for (int e = tid; e < NCLS * HW_; e += 256)
        s_c[e] = g_logits[(long)b * NCLS * HW_ + e];
    __syncthreads();

    int cl = tid & 31, np = tid >> 5;   // warp np handles n = np + 8j
    float acc[10];
#pragma unroll
    for (int j = 0; j < 10; j++) acc[j] = 0.f;

    const float4* x4 = (const float4*)(s_x + cl * HW_);
    for (int q = 0; q < HW_ / 4; q++) {
        float4 xv = x4[q];
#pragma unroll
        for (int j = 0; j < 10; j++) {
            float4 cv = *(const float4*)(s_c + (np + 8 * j) * HW_ + 4 * q);
            acc[j] = fmaf(xv.x, cv.x, acc[j]);
            acc[j] = fmaf(xv.y, cv.y, acc[j]);
            acc[j] = fmaf(xv.z, cv.z, acc[j]);
            acc[j] = fmaf(xv.w, cv.w, acc[j]);
        }
    }
#pragma unroll
    for (int j = 0; j < 10; j++) {
        int n = np + 8 * j;
        out[((long)b * NCLS + n) * C_ + c0 + cl] = acc[j];
    }
}

// ---------------- launch ----------------
extern "C" void kernel_launch(void* const* d_in, const int* in_sizes, int n_in,
                              void* d_out, int out_size) {
    (void)in_sizes; (void)n_in; (void)out_size;
    const float* img  = (const float*)d_in[0];  // [B,C,H,W]
    const float* wf   = (const float*)d_in[1];  // [N,WD]
    const float* fc1w = (const float*)d_in[2];  // [ID,C]
    const float* fc2w = (const float*)d_in[3];  // [ID,WD]
    const float* fc3w = (const float*)d_in[4];  // [ID,ID]
    // d_in[5] fc3_b, d_in[7] fc4_b: constant over softmax axis -> cancel
    const float* fc4w = (const float*)d_in[6];  // [1,ID]
    float* out = (float*)d_out;                 // [B,N,C] fp32

    cudaFuncSetAttribute(k_mma,  cudaFuncAttributeMaxDynamicSharedMemorySize, MMA_SMEM);
    cudaFuncSetAttribute(k_pool, cudaFuncAttributeMaxDynamicSharedMemorySize, POOL_SMEM);

    k_prep   <<<PREP_BLOCKS, 256>>>(img, wf, fc1w, fc2w, fc3w, fc4w);
    k_mma    <<<dim3(8, 7, 2), 256, MMA_SMEM>>>();
    k_logits <<<392, 256>>>();
    k_softmax<<<40, 256>>>();
    k_pool   <<<dim3(64, 4), 256, POOL_SMEM>>>(img, out);
}